// round 14
// baseline (speedup 1.0000x reference)
#include <cuda_runtime.h>
#include <cuda_bf16.h>
#include <cuda_fp16.h>
#include <cuda_fp8.h>
#include <math.h>

// Problem constants
#define NMAX 50000
#define EMAX 800000
#define HDIM 128
#define GCNT 128
#define CCNT 10
#define SCAN_BLK 512

// ---------------- device scratch (no cudaMalloc allowed) ----------------
__device__ unsigned g_h8[NMAX * 32];    // GEMM output, packed e4m3 x4 (128B/row)
__device__ unsigned g_aggb[NMAX * 64];  // agg1 output, packed bf16x2 (GEMM2 A)
__device__ float g_h3[NMAX * 16];       // layer-3 projected features (padded C)
__device__ float g_deg[NMAX];
__device__ float g_dinv[NMAX];
__device__ int   g_cnt[NMAX];
__device__ int   g_row[NMAX + 1];
__device__ int   g_cur[NMAX];
__device__ int   g_bsum[128];
__device__ uint2 g_edge[EMAX];          // packed (src, bits(ew*dinv[src]))
__device__ float g_psum[GCNT * CCNT];
__device__ float g_pcnt[GCNT];

// ---------------- fp8 helpers ----------------
__device__ __forceinline__ float4 fp8x4_to_float4(unsigned u) {
    __half2_raw lo = __nv_cvt_fp8x2_to_halfraw2((__nv_fp8x2_storage_t)(u & 0xFFFFu), __NV_E4M3);
    __half2_raw hi = __nv_cvt_fp8x2_to_halfraw2((__nv_fp8x2_storage_t)(u >> 16), __NV_E4M3);
    float2 f0 = __half22float2(*(__half2*)&lo);
    float2 f1 = __half22float2(*(__half2*)&hi);
    return make_float4(f0.x, f0.y, f1.x, f1.y);
}

__device__ __forceinline__ unsigned f2_to_fp8x2(float a, float b) {
    return (unsigned)__nv_cvt_float2_to_fp8x2(make_float2(a, b), __NV_SATFINITE, __NV_E4M3);
}

// ---------------- preprocessing ----------------

__global__ void k_init(int n) {
    int i = blockIdx.x * blockDim.x + threadIdx.x;
    if (i < n) { g_deg[i] = 1.0f; g_cnt[i] = 0; }   // self-loop weight 1
    if (i < GCNT * CCNT) g_psum[i] = 0.0f;
    if (i < GCNT) g_pcnt[i] = 0.0f;
}

__global__ void k_count(const int* __restrict__ dst, const float* __restrict__ ew, int e) {
    int i = blockIdx.x * blockDim.x + threadIdx.x;
    if (i >= e) return;
    int d = dst[i];
    atomicAdd(&g_deg[d], ew[i]);
    atomicAdd(&g_cnt[d], 1);
}

__global__ void k_scan1(int n) {
    __shared__ int sd[SCAN_BLK];
    int tid = threadIdx.x;
    int i = blockIdx.x * SCAN_BLK + tid;
    int v = (i < n) ? g_cnt[i] : 0;
    sd[tid] = v;
    __syncthreads();
#pragma unroll
    for (int off = 1; off < SCAN_BLK; off <<= 1) {
        int t = (tid >= off) ? sd[tid - off] : 0;
        __syncthreads();
        sd[tid] += t;
        __syncthreads();
    }
    if (i < n) g_row[i] = sd[tid] - v;
    if (tid == SCAN_BLK - 1) g_bsum[blockIdx.x] = sd[SCAN_BLK - 1];
}

// scan3 with scan2 folded in: each block sums the preceding block-sums itself.
__global__ void k_scan3(int n, int e, int nb) {
    __shared__ int sb[128];
    int tid = threadIdx.x;
    if (tid < 128) sb[tid] = (tid < nb) ? g_bsum[tid] : 0;
    __syncthreads();
    int b = blockIdx.x;
    int off = 0;
    for (int k = 0; k < b; k++) off += sb[k];
    int i = b * SCAN_BLK + tid;
    if (i < n) {
        int r = g_row[i] + off;
        g_row[i] = r;
        g_cur[i] = r;
        float d = g_deg[i];
        g_dinv[i] = (d > 0.0f) ? rsqrtf(d) : 0.0f;
    }
    if (b == 0 && tid == 0) g_row[n] = e;
}

__global__ void k_scatter(const int* __restrict__ src, const int* __restrict__ dst,
                          const float* __restrict__ ew, int e) {
    int i = blockIdx.x * blockDim.x + threadIdx.x;
    if (i >= e) return;
    int s = src[i], d = dst[i];
    int pos = atomicAdd(&g_cur[d], 1);
    g_edge[pos] = make_uint2((unsigned)s, __float_as_uint(ew[i] * g_dinv[s]));
}

// ---------------- tensor-core GEMM (single tf32, cvt-at-load) ----------------
// [M,128] @ [128,128] -> e4m3 packed. A is fp32 (cvt.rna->tf32) or bf16 (exact).
__device__ __forceinline__ void mma_tf32(float* c, const unsigned* a,
                                         unsigned b0, unsigned b1) {
    asm volatile(
        "mma.sync.aligned.m16n8k8.row.col.f32.tf32.tf32.f32 "
        "{%0,%1,%2,%3}, {%4,%5,%6,%7}, {%8,%9}, {%0,%1,%2,%3};\n"
        : "+f"(c[0]), "+f"(c[1]), "+f"(c[2]), "+f"(c[3])
        : "r"(a[0]), "r"(a[1]), "r"(a[2]), "r"(a[3]), "r"(b0), "r"(b1));
}

__device__ __forceinline__ float to_tf32(float v) {
    // round-to-nearest tf32 (unbiased — truncation bias would accumulate over K)
    float r;
    asm("cvt.rna.tf32.f32 %0, %1;" : "=f"(r) : "f"(v));
    return r;
}

// load 8 consecutive A elements (row-major, 128 cols) as tf32-ready floats
template<bool BF16A>
__device__ __forceinline__ void loadA8(const void* Abase, size_t row, int col,
                                       bool ok, float* v) {
    if (!ok) {
#pragma unroll
        for (int q = 0; q < 8; q++) v[q] = 0.0f;
        return;
    }
    if (BF16A) {
        const __nv_bfloat16* A = (const __nv_bfloat16*)Abase;
        uint4 u = *(const uint4*)(A + row * 128 + col);
        float2 f0 = __bfloat1622float2(*(const __nv_bfloat162*)&u.x);
        float2 f1 = __bfloat1622float2(*(const __nv_bfloat162*)&u.y);
        float2 f2 = __bfloat1622float2(*(const __nv_bfloat162*)&u.z);
        float2 f3 = __bfloat1622float2(*(const __nv_bfloat162*)&u.w);
        v[0] = f0.x; v[1] = f0.y; v[2] = f1.x; v[3] = f1.y;
        v[4] = f2.x; v[5] = f2.y; v[6] = f3.x; v[7] = f3.y;   // bf16 ⊂ tf32: exact
    } else {
        const float* A = (const float*)Abase;
        float4 a0 = *(const float4*)(A + row * 128 + col);
        float4 a1 = *(const float4*)(A + row * 128 + col + 4);
        v[0] = to_tf32(a0.x); v[1] = to_tf32(a0.y); v[2] = to_tf32(a0.z); v[3] = to_tf32(a0.w);
        v[4] = to_tf32(a1.x); v[5] = to_tf32(a1.y); v[6] = to_tf32(a1.z); v[7] = to_tf32(a1.w);
    }
}

template<bool BF16A>
__global__ __launch_bounds__(256, 2)
void sgemm128_tf32(const void* __restrict__ A, const float* __restrict__ B,
                   unsigned* __restrict__ C8, int M) {
    __shared__ float As[2][128][20];
    __shared__ float Bs[2][16][136];

    int tid  = threadIdx.x;
    int warp = tid >> 5;
    int lane = tid & 31;
    int g = lane >> 2;
    int t = lane & 3;
    int r0 = warp * 16;
    int rowBase = blockIdx.x * 128;

    int aRow = tid >> 1;
    int aOff = (tid & 1) * 8;
    int bRow = tid >> 4;
    int bOff = (tid & 15) * 8;

    bool aOk = (rowBase + aRow) < M;
    size_t aGRow = (size_t)(aOk ? rowBase + aRow : 0);

    float acc[16][4];
#pragma unroll
    for (int j = 0; j < 16; j++)
#pragma unroll
        for (int q = 0; q < 4; q++) acc[j][q] = 0.0f;

    // preload stage 0
    {
        float av[8];
        loadA8<BF16A>(A, aGRow, aOff, aOk, av);
#pragma unroll
        for (int q = 0; q < 8; q++) As[0][aRow][aOff + q] = av[q];
        float4 b0 = *(const float4*)(B + (size_t)bRow * 128 + bOff);
        float4 b1 = *(const float4*)(B + (size_t)bRow * 128 + bOff + 4);
        Bs[0][bRow][bOff + 0] = to_tf32(b0.x); Bs[0][bRow][bOff + 1] = to_tf32(b0.y);
        Bs[0][bRow][bOff + 2] = to_tf32(b0.z); Bs[0][bRow][bOff + 3] = to_tf32(b0.w);
        Bs[0][bRow][bOff + 4] = to_tf32(b1.x); Bs[0][bRow][bOff + 5] = to_tf32(b1.y);
        Bs[0][bRow][bOff + 6] = to_tf32(b1.z); Bs[0][bRow][bOff + 7] = to_tf32(b1.w);
    }
    __syncthreads();

    int p = 0;
    for (int k0 = 0; k0 < 128; k0 += 16) {
        bool more = (k0 + 16) < 128;
        float pav[8];
        float4 pb0, pb1;
        if (more) {
            loadA8<BF16A>(A, aGRow, k0 + 16 + aOff, aOk, pav);
            pb0 = *(const float4*)(B + (size_t)(k0 + 16 + bRow) * 128 + bOff);
            pb1 = *(const float4*)(B + (size_t)(k0 + 16 + bRow) * 128 + bOff + 4);
        }

#pragma unroll
        for (int kk = 0; kk < 16; kk += 8) {
            unsigned a[4];
            a[0] = __float_as_uint(As[p][r0 + g    ][kk + t]);
            a[1] = __float_as_uint(As[p][r0 + g + 8][kk + t]);
            a[2] = __float_as_uint(As[p][r0 + g    ][kk + t + 4]);
            a[3] = __float_as_uint(As[p][r0 + g + 8][kk + t + 4]);
#pragma unroll
            for (int j = 0; j < 16; j++) {
                unsigned b0 = __float_as_uint(Bs[p][kk + t    ][j * 8 + g]);
                unsigned b1 = __float_as_uint(Bs[p][kk + t + 4][j * 8 + g]);
                mma_tf32(acc[j], a, b0, b1);
            }
        }

        if (more) {
            int q = p ^ 1;
#pragma unroll
            for (int qq = 0; qq < 8; qq++) As[q][aRow][aOff + qq] = pav[qq];
            Bs[q][bRow][bOff + 0] = to_tf32(pb0.x); Bs[q][bRow][bOff + 1] = to_tf32(pb0.y);
            Bs[q][bRow][bOff + 2] = to_tf32(pb0.z); Bs[q][bRow][bOff + 3] = to_tf32(pb0.w);
            Bs[q][bRow][bOff + 4] = to_tf32(pb1.x); Bs[q][bRow][bOff + 5] = to_tf32(pb1.y);
            Bs[q][bRow][bOff + 6] = to_tf32(pb1.z); Bs[q][bRow][bOff + 7] = to_tf32(pb1.w);
            __syncthreads();
            p = q;
        }
    }

    // epilogue: pack to e4m3. Thread t owns cols (8j+2t, 8j+2t+1); lanes t and
    // t^1 combine into one 4-byte word (cols 4w..4w+3), even-t lanes store.
    int rA = rowBase + r0 + g;
    int rB = rA + 8;
#pragma unroll
    for (int j = 0; j < 16; j++) {
        unsigned myA = f2_to_fp8x2(acc[j][0], acc[j][1]);
        unsigned myB = f2_to_fp8x2(acc[j][2], acc[j][3]);
        unsigned otA = __shfl_xor_sync(0xffffffffu, myA, 1);
        unsigned otB = __shfl_xor_sync(0xffffffffu, myB, 1);
        if ((t & 1) == 0) {
            int widx = 2 * j + (t >> 1);
            if (rA < M) C8[(size_t)rA * 32 + widx] = (myA & 0xFFFFu) | (otA << 16);
            if (rB < M) C8[(size_t)rB * 32 + widx] = (myB & 0xFFFFu) | (otB << 16);
        }
    }
}

// ---------------- shared gather body (fp8 in, fp32 acc) ----------------
// lane covers cols 4*lane..4*lane+3; one uint32 (4 x e4m3) per lane per row.
__device__ __forceinline__ float4 gather_node8(const unsigned* __restrict__ h8,
                                               int gw, int lane, float di) {
    float4 acc;
    {
        float4 f = fp8x4_to_float4(h8[(size_t)gw * 32 + lane]);
        acc.x = f.x * di; acc.y = f.y * di;
        acc.z = f.z * di; acc.w = f.w * di;
    }
    int j = g_row[gw];
    int end = g_row[gw + 1];
    for (; j + 4 <= end; j += 4) {
        uint2 e0 = g_edge[j], e1 = g_edge[j + 1], e2 = g_edge[j + 2], e3 = g_edge[j + 3];
        float w0 = __uint_as_float(e0.y), w1 = __uint_as_float(e1.y);
        float w2 = __uint_as_float(e2.y), w3 = __uint_as_float(e3.y);
        unsigned u0 = h8[(size_t)e0.x * 32 + lane];
        unsigned u1 = h8[(size_t)e1.x * 32 + lane];
        unsigned u2 = h8[(size_t)e2.x * 32 + lane];
        unsigned u3 = h8[(size_t)e3.x * 32 + lane];
        float4 f0 = fp8x4_to_float4(u0);
        float4 f1 = fp8x4_to_float4(u1);
        float4 f2 = fp8x4_to_float4(u2);
        float4 f3 = fp8x4_to_float4(u3);
        acc.x = fmaf(w0, f0.x, acc.x); acc.y = fmaf(w0, f0.y, acc.y);
        acc.z = fmaf(w0, f0.z, acc.z); acc.w = fmaf(w0, f0.w, acc.w);
        acc.x = fmaf(w1, f1.x, acc.x); acc.y = fmaf(w1, f1.y, acc.y);
        acc.z = fmaf(w1, f1.z, acc.z); acc.w = fmaf(w1, f1.w, acc.w);
        acc.x = fmaf(w2, f2.x, acc.x); acc.y = fmaf(w2, f2.y, acc.y);
        acc.z = fmaf(w2, f2.z, acc.z); acc.w = fmaf(w2, f2.w, acc.w);
        acc.x = fmaf(w3, f3.x, acc.x); acc.y = fmaf(w3, f3.y, acc.y);
        acc.z = fmaf(w3, f3.z, acc.z); acc.w = fmaf(w3, f3.w, acc.w);
    }
    for (; j < end; j++) {
        uint2 ed = g_edge[j];
        float w = __uint_as_float(ed.y);
        float4 f = fp8x4_to_float4(h8[(size_t)ed.x * 32 + lane]);
        acc.x = fmaf(w, f.x, acc.x); acc.y = fmaf(w, f.y, acc.y);
        acc.z = fmaf(w, f.z, acc.z); acc.w = fmaf(w, f.w, acc.w);
    }
    return acc;
}

// ---------------- layer-1 aggregation: out packed bf16 (GEMM2 A) ----------------
__global__ __launch_bounds__(256)
void agg_h128(const unsigned* __restrict__ h8, unsigned* __restrict__ outb,
              const float* __restrict__ bias, int n) {
    int gw = (blockIdx.x * blockDim.x + threadIdx.x) >> 5;
    if (gw >= n) return;
    int lane = threadIdx.x & 31;
    float di = g_dinv[gw];
    float4 acc = gather_node8(h8, gw, lane, di);

    float4 bb = ((const float4*)bias)[lane];
    acc.x = fmaxf(fmaf(acc.x, di, bb.x), 0.f);
    acc.y = fmaxf(fmaf(acc.y, di, bb.y), 0.f);
    acc.z = fmaxf(fmaf(acc.z, di, bb.z), 0.f);
    acc.w = fmaxf(fmaf(acc.w, di, bb.w), 0.f);

    __nv_bfloat162 v0 = __float22bfloat162_rn(make_float2(acc.x, acc.y));
    __nv_bfloat162 v1 = __float22bfloat162_rn(make_float2(acc.z, acc.w));
    ((uint2*)outb)[(size_t)gw * 32 + lane] = make_uint2(*(unsigned*)&v0, *(unsigned*)&v1);
}

// ---------------- layer-2 aggregation + fused W3 projection ----------------
__global__ __launch_bounds__(512)
void agg_h128_w3(const unsigned* __restrict__ h8, const float* __restrict__ bias,
                 const float* __restrict__ W3, int n) {
    __shared__ float Wsc[CCNT][HDIM];
    for (int idx = threadIdx.x; idx < HDIM * CCNT; idx += 512) {
        int k = idx / CCNT, c = idx % CCNT;
        Wsc[c][k] = W3[idx];
    }
    __syncthreads();

    int gw = (blockIdx.x * blockDim.x + threadIdx.x) >> 5;
    if (gw >= n) return;
    int lane = threadIdx.x & 31;
    float di = g_dinv[gw];
    float4 acc = gather_node8(h8, gw, lane, di);

    float4 bb = ((const float4*)bias)[lane];
    acc.x = fmaxf(fmaf(acc.x, di, bb.x), 0.f);
    acc.y = fmaxf(fmaf(acc.y, di, bb.y), 0.f);
    acc.z = fmaxf(fmaf(acc.z, di, bb.z), 0.f);
    acc.w = fmaxf(fmaf(acc.w, di, bb.w), 0.f);

    float p[CCNT];
#pragma unroll
    for (int c = 0; c < CCNT; c++) {
        float4 w = *(const float4*)&Wsc[c][4 * lane];
        p[c] = acc.x * w.x + acc.y * w.y + acc.z * w.z + acc.w * w.w;
    }
#pragma unroll
    for (int c = 0; c < CCNT; c++) {
#pragma unroll
        for (int off = 16; off > 0; off >>= 1)
            p[c] += __shfl_xor_sync(0xffffffffu, p[c], off);
    }
    if (lane == 0) {
        float* dst = &g_h3[(size_t)gw * 16];
#pragma unroll
        for (int c = 0; c < CCNT; c++) dst[c] = p[c];
    }
}

// ---------------- layer 3 aggregation + pool ----------------
__global__ __launch_bounds__(256)
void agg_c16_pool(const int* __restrict__ batch, const float* __restrict__ b3, int n) {
    int gw = (blockIdx.x * blockDim.x + threadIdx.x) >> 5;
    if (gw >= n) return;
    int lane = threadIdx.x & 31;
    bool active = (lane < CCNT);

    float di = g_dinv[gw];
    float acc = 0.0f;
    if (active) acc = g_h3[gw * 16 + lane] * di;

    int j = g_row[gw];
    int end = g_row[gw + 1];
    for (; j + 4 <= end; j += 4) {
        uint2 e0 = g_edge[j], e1 = g_edge[j + 1], e2 = g_edge[j + 2], e3 = g_edge[j + 3];
        if (active) {
            acc = fmaf(__uint_as_float(e0.y), g_h3[(size_t)e0.x * 16 + lane], acc);
            acc = fmaf(__uint_as_float(e1.y), g_h3[(size_t)e1.x * 16 + lane], acc);
            acc = fmaf(__uint_as_float(e2.y), g_h3[(size_t)e2.x * 16 + lane], acc);
            acc = fmaf(__uint_as_float(e3.y), g_h3[(size_t)e3.x * 16 + lane], acc);
        }
    }
    for (; j < end; j++) {
        uint2 ed = g_edge[j];
        if (active) acc = fmaf(__uint_as_float(ed.y), g_h3[(size_t)ed.x * 16 + lane], acc);
    }

    int g = batch[gw];
    if (active) {
        acc = fmaf(acc, di, b3[lane]);
        atomicAdd(&g_psum[g * CCNT + lane], acc);
    }
    if (lane == 0) atomicAdd(&g_pcnt[g], 1.0f);
}

// ---------------- final: mean + log_softmax ----------------
__global__ void k_finalize(float* __restrict__ out) {
    int g = threadIdx.x;
    if (g >= GCNT) return;
    float c = fmaxf(g_pcnt[g], 1.0f);
    float v[CCNT];
    float m = -1e30f;
#pragma unroll
    for (int j = 0; j < CCNT; j++) {
        v[j] = g_psum[g * CCNT + j] / c;
        m = fmaxf(m, v[j]);
    }
    float s = 0.0f;
#pragma unroll
    for (int j = 0; j < CCNT; j++) s += expf(v[j] - m);
    float lse = logf(s) + m;
#pragma unroll
    for (int j = 0; j < CCNT; j++) out[g * CCNT + j] = v[j] - lse;
}

// ---------------- launch ----------------
extern "C" void kernel_launch(void* const* d_in, const int* in_sizes, int n_in,
                              void* d_out, int out_size) {
    const float* x    = (const float*)d_in[0];
    const int*   ei   = (const int*)d_in[1];
    const float* ea   = (const float*)d_in[2];
    const int*   bat  = (const int*)d_in[3];
    const float* W1   = (const float*)d_in[4];
    const float* b1   = (const float*)d_in[5];
    const float* W2   = (const float*)d_in[6];
    const float* b2   = (const float*)d_in[7];
    const float* W3   = (const float*)d_in[8];
    const float* b3   = (const float*)d_in[9];
    float* out = (float*)d_out;

    int n = in_sizes[0] / HDIM;   // 50000
    int e = in_sizes[1] / 2;      // 800000
    const int* src = ei;
    const int* dst = ei + e;

    unsigned *gh8, *gaggb;
    cudaGetSymbolAddress((void**)&gh8, g_h8);
    cudaGetSymbolAddress((void**)&gaggb, g_aggb);

    int nb = (n + SCAN_BLK - 1) / SCAN_BLK;
    int gemmBlocks = (n + 127) / 128;
    int aggBlocks256 = (n * 32 + 255) / 256;
    int aggBlocks512 = (n * 32 + 511) / 512;

    cudaStream_t s0 = (cudaStream_t)0;

    // fork a side stream: layer-1 GEMM is independent of CSR preprocessing
    cudaStream_t s2;
    cudaStreamCreateWithFlags(&s2, cudaStreamNonBlocking);
    cudaEvent_t evFork, evJoin;
    cudaEventCreateWithFlags(&evFork, cudaEventDisableTiming);
    cudaEventCreateWithFlags(&evJoin, cudaEventDisableTiming);

    cudaEventRecord(evFork, s0);
    cudaStreamWaitEvent(s2, evFork, 0);
    sgemm128_tf32<false><<<gemmBlocks, 256, 0, s2>>>(x, W1, gh8, n);  // h = x@W1
    cudaEventRecord(evJoin, s2);

    // preprocessing on main stream (concurrent with the GEMM above)
    k_init<<<(n + 255) / 256, 256, 0, s0>>>(n);
    k_count<<<(e + 255) / 256, 256, 0, s0>>>(dst, ea, e);
    k_scan1<<<nb, SCAN_BLK, 0, s0>>>(n);
    k_scan3<<<nb, SCAN_BLK, 0, s0>>>(n, e, nb);
    k_scatter<<<(e + 255) / 256, 256, 0, s0>>>(src, dst, ea, e);

    // join: aggregation needs both CSR and h
    cudaStreamWaitEvent(s0, evJoin, 0);
    agg_h128<<<aggBlocks256, 256, 0, s0>>>(gh8, gaggb, b1, n);

    // layer 2 (bf16 A) + fused W3 projection
    sgemm128_tf32<true><<<gemmBlocks, 256, 0, s0>>>(gaggb, W2, gh8, n);
    agg_h128_w3<<<aggBlocks512, 512, 0, s0>>>(gh8, b2, W3, n);

    // layer 3 aggregation + pool, then finalize
    agg_c16_pool<<<aggBlocks256, 256, 0, s0>>>(bat, b3, n);
    k_finalize<<<1, 128, 0, s0>>>(out);
    // NOTE: s2/events intentionally not destroyed — kernel_launch is invoked
    // only for the correctness run and one graph capture.
}

// round 15
// speedup vs baseline: 1.3543x; 1.3543x over previous
#include <cuda_runtime.h>
#include <cuda_bf16.h>
#include <math.h>

// Problem constants
#define NMAX 50000
#define EMAX 800000
#define HDIM 128
#define GCNT 128
#define CCNT 10
#define SCAN_BLK 512

// ---------------- device scratch (no cudaMalloc allowed) ----------------
__device__ unsigned g_hb[NMAX * 64];    // GEMM output, packed bf16x2
__device__ unsigned g_aggb[NMAX * 64];  // agg1 output, packed bf16x2 (GEMM2 A)
__device__ float g_h3[NMAX * 16];       // layer-3 projected features (padded C)
__device__ float g_deg[NMAX];
__device__ float g_dinv[NMAX];
__device__ int   g_cnt[NMAX];
__device__ int   g_row[NMAX + 1];
__device__ int   g_cur[NMAX];
__device__ int   g_bsum[128];
__device__ int   g_scanArrive;          // zero-init; self-resets every call
__device__ int   g_scanDone;            // zero-init; self-resets every call
__device__ uint2 g_edge[EMAX];          // packed (src, bits(ew*dinv[src]))
__device__ float g_psum[GCNT * CCNT];
__device__ float g_pcnt[GCNT];

// ---------------- preprocessing ----------------

__global__ void k_init(int n) {
    int i = blockIdx.x * blockDim.x + threadIdx.x;
    if (i < n) { g_deg[i] = 1.0f; g_cnt[i] = 0; }   // self-loop weight 1
    if (i < GCNT * CCNT) g_psum[i] = 0.0f;
    if (i < GCNT) g_pcnt[i] = 0.0f;
}

__global__ void k_count(const int* __restrict__ dst, const float* __restrict__ ew, int e) {
    int i = blockIdx.x * blockDim.x + threadIdx.x;
    if (i >= e) return;
    int d = dst[i];
    atomicAdd(&g_deg[d], ew[i]);
    atomicAdd(&g_cnt[d], 1);
}

// single-launch exclusive scan of g_cnt -> g_row/g_cur (+dinv), using a
// global spin barrier. Grid = 98 blocks <= 148 SMs: all wave-1 resident,
// so the barrier cannot deadlock. Arrive/done counters self-reset so the
// kernel is replay-deterministic under graph capture.
__global__ void k_scan(int n, int e, int nb) {
    __shared__ int sd[SCAN_BLK];
    __shared__ int sb[128];
    int tid = threadIdx.x;
    int b = blockIdx.x;
    int i = b * SCAN_BLK + tid;

    int v = (i < n) ? g_cnt[i] : 0;
    sd[tid] = v;
    __syncthreads();
#pragma unroll
    for (int off = 1; off < SCAN_BLK; off <<= 1) {
        int t = (tid >= off) ? sd[tid - off] : 0;
        __syncthreads();
        sd[tid] += t;
        __syncthreads();
    }
    int local = sd[tid] - v;   // exclusive within block
    if (tid == SCAN_BLK - 1) g_bsum[b] = sd[SCAN_BLK - 1];

    // global barrier: all blocks' bsum visible
    __threadfence();
    __syncthreads();
    if (tid == 0) {
        atomicAdd(&g_scanArrive, 1);
        while (atomicAdd(&g_scanArrive, 0) < nb) { }
    }
    __syncthreads();

    if (tid < 128) sb[tid] = (tid < nb) ? g_bsum[tid] : 0;
    __syncthreads();
    int off = 0;
    for (int k = 0; k < b; k++) off += sb[k];

    if (i < n) {
        int r = local + off;
        g_row[i] = r;
        g_cur[i] = r;
        float d = g_deg[i];
        g_dinv[i] = (d > 0.0f) ? rsqrtf(d) : 0.0f;
    }
    if (b == 0 && tid == 0) g_row[n] = e;

    // reset counters once every block has passed the spin
    __syncthreads();
    if (tid == 0) {
        int old = atomicAdd(&g_scanDone, 1);
        if (old == nb - 1) { g_scanArrive = 0; g_scanDone = 0; }
    }
}

__global__ void k_scatter(const int* __restrict__ src, const int* __restrict__ dst,
                          const float* __restrict__ ew, int e) {
    int i = blockIdx.x * blockDim.x + threadIdx.x;
    if (i >= e) return;
    int s = src[i], d = dst[i];
    int pos = atomicAdd(&g_cur[d], 1);
    g_edge[pos] = make_uint2((unsigned)s, __float_as_uint(ew[i] * g_dinv[s]));
}

// ---------------- tensor-core GEMM (single tf32, cvt-at-load) ----------------
// [M,128] @ [128,128] -> bf16x2. A is fp32 (cvt.rna->tf32) or bf16 (exact).
__device__ __forceinline__ void mma_tf32(float* c, const unsigned* a,
                                         unsigned b0, unsigned b1) {
    asm volatile(
        "mma.sync.aligned.m16n8k8.row.col.f32.tf32.tf32.f32 "
        "{%0,%1,%2,%3}, {%4,%5,%6,%7}, {%8,%9}, {%0,%1,%2,%3};\n"
        : "+f"(c[0]), "+f"(c[1]), "+f"(c[2]), "+f"(c[3])
        : "r"(a[0]), "r"(a[1]), "r"(a[2]), "r"(a[3]), "r"(b0), "r"(b1));
}

__device__ __forceinline__ float to_tf32(float v) {
    float r;
    asm("cvt.rna.tf32.f32 %0, %1;" : "=f"(r) : "f"(v));
    return r;
}

template<bool BF16A>
__device__ __forceinline__ void loadA8(const void* Abase, size_t row, int col,
                                       bool ok, float* v) {
    if (!ok) {
#pragma unroll
        for (int q = 0; q < 8; q++) v[q] = 0.0f;
        return;
    }
    if (BF16A) {
        const __nv_bfloat16* A = (const __nv_bfloat16*)Abase;
        uint4 u = *(const uint4*)(A + row * 128 + col);
        float2 f0 = __bfloat1622float2(*(const __nv_bfloat162*)&u.x);
        float2 f1 = __bfloat1622float2(*(const __nv_bfloat162*)&u.y);
        float2 f2 = __bfloat1622float2(*(const __nv_bfloat162*)&u.z);
        float2 f3 = __bfloat1622float2(*(const __nv_bfloat162*)&u.w);
        v[0] = f0.x; v[1] = f0.y; v[2] = f1.x; v[3] = f1.y;
        v[4] = f2.x; v[5] = f2.y; v[6] = f3.x; v[7] = f3.y;   // bf16 ⊂ tf32: exact
    } else {
        const float* A = (const float*)Abase;
        float4 a0 = *(const float4*)(A + row * 128 + col);
        float4 a1 = *(const float4*)(A + row * 128 + col + 4);
        v[0] = to_tf32(a0.x); v[1] = to_tf32(a0.y); v[2] = to_tf32(a0.z); v[3] = to_tf32(a0.w);
        v[4] = to_tf32(a1.x); v[5] = to_tf32(a1.y); v[6] = to_tf32(a1.z); v[7] = to_tf32(a1.w);
    }
}

template<bool BF16A>
__global__ __launch_bounds__(256, 2)
void sgemm128_tf32(const void* __restrict__ A, const float* __restrict__ B,
                   unsigned* __restrict__ Cb, int M) {
    __shared__ float As[2][128][20];
    __shared__ float Bs[2][16][136];

    int tid  = threadIdx.x;
    int warp = tid >> 5;
    int lane = tid & 31;
    int g = lane >> 2;
    int t = lane & 3;
    int r0 = warp * 16;
    int rowBase = blockIdx.x * 128;

    int aRow = tid >> 1;
    int aOff = (tid & 1) * 8;
    int bRow = tid >> 4;
    int bOff = (tid & 15) * 8;

    bool aOk = (rowBase + aRow) < M;
    size_t aGRow = (size_t)(aOk ? rowBase + aRow : 0);

    float acc[16][4];
#pragma unroll
    for (int j = 0; j < 16; j++)
#pragma unroll
        for (int q = 0; q < 4; q++) acc[j][q] = 0.0f;

    // preload stage 0
    {
        float av[8];
        loadA8<BF16A>(A, aGRow, aOff, aOk, av);
#pragma unroll
        for (int q = 0; q < 8; q++) As[0][aRow][aOff + q] = av[q];
        float4 b0 = *(const float4*)(B + (size_t)bRow * 128 + bOff);
        float4 b1 = *(const float4*)(B + (size_t)bRow * 128 + bOff + 4);
        Bs[0][bRow][bOff + 0] = to_tf32(b0.x); Bs[0][bRow][bOff + 1] = to_tf32(b0.y);
        Bs[0][bRow][bOff + 2] = to_tf32(b0.z); Bs[0][bRow][bOff + 3] = to_tf32(b0.w);
        Bs[0][bRow][bOff + 4] = to_tf32(b1.x); Bs[0][bRow][bOff + 5] = to_tf32(b1.y);
        Bs[0][bRow][bOff + 6] = to_tf32(b1.z); Bs[0][bRow][bOff + 7] = to_tf32(b1.w);
    }
    __syncthreads();

    int p = 0;
    for (int k0 = 0; k0 < 128; k0 += 16) {
        bool more = (k0 + 16) < 128;
        float pav[8];
        float4 pb0, pb1;
        if (more) {
            loadA8<BF16A>(A, aGRow, k0 + 16 + aOff, aOk, pav);
            pb0 = *(const float4*)(B + (size_t)(k0 + 16 + bRow) * 128 + bOff);
            pb1 = *(const float4*)(B + (size_t)(k0 + 16 + bRow) * 128 + bOff + 4);
        }

#pragma unroll
        for (int kk = 0; kk < 16; kk += 8) {
            unsigned a[4];
            a[0] = __float_as_uint(As[p][r0 + g    ][kk + t]);
            a[1] = __float_as_uint(As[p][r0 + g + 8][kk + t]);
            a[2] = __float_as_uint(As[p][r0 + g    ][kk + t + 4]);
            a[3] = __float_as_uint(As[p][r0 + g + 8][kk + t + 4]);
#pragma unroll
            for (int j = 0; j < 16; j++) {
                unsigned b0 = __float_as_uint(Bs[p][kk + t    ][j * 8 + g]);
                unsigned b1 = __float_as_uint(Bs[p][kk + t + 4][j * 8 + g]);
                mma_tf32(acc[j], a, b0, b1);
            }
        }

        if (more) {
            int q = p ^ 1;
#pragma unroll
            for (int qq = 0; qq < 8; qq++) As[q][aRow][aOff + qq] = pav[qq];
            Bs[q][bRow][bOff + 0] = to_tf32(pb0.x); Bs[q][bRow][bOff + 1] = to_tf32(pb0.y);
            Bs[q][bRow][bOff + 2] = to_tf32(pb0.z); Bs[q][bRow][bOff + 3] = to_tf32(pb0.w);
            Bs[q][bRow][bOff + 4] = to_tf32(pb1.x); Bs[q][bRow][bOff + 5] = to_tf32(pb1.y);
            Bs[q][bRow][bOff + 6] = to_tf32(pb1.z); Bs[q][bRow][bOff + 7] = to_tf32(pb1.w);
            __syncthreads();
            p = q;
        }
    }

    int rA = rowBase + r0 + g;
    int rB = rA + 8;
#pragma unroll
    for (int j = 0; j < 16; j++) {
        int widx = j * 4 + t;
        if (rA < M) {
            __nv_bfloat162 v = __float22bfloat162_rn(make_float2(acc[j][0], acc[j][1]));
            Cb[(size_t)rA * 64 + widx] = *(unsigned*)&v;
        }
        if (rB < M) {
            __nv_bfloat162 v = __float22bfloat162_rn(make_float2(acc[j][2], acc[j][3]));
            Cb[(size_t)rB * 64 + widx] = *(unsigned*)&v;
        }
    }
}

// ---------------- shared gather body (bf16 in, fp32 acc) ----------------
__device__ __forceinline__ float4 gather_node(const uint2* __restrict__ h2,
                                              int gw, int lane, float di) {
    float4 acc;
    {
        uint2 u = h2[(size_t)gw * 32 + lane];
        float2 f0 = __bfloat1622float2(*(const __nv_bfloat162*)&u.x);
        float2 f1 = __bfloat1622float2(*(const __nv_bfloat162*)&u.y);
        acc.x = f0.x * di; acc.y = f0.y * di;
        acc.z = f1.x * di; acc.w = f1.y * di;
    }
    int j = g_row[gw];
    int end = g_row[gw + 1];
    for (; j + 4 <= end; j += 4) {
        uint2 e0 = g_edge[j], e1 = g_edge[j + 1], e2 = g_edge[j + 2], e3 = g_edge[j + 3];
        float w0 = __uint_as_float(e0.y), w1 = __uint_as_float(e1.y);
        float w2 = __uint_as_float(e2.y), w3 = __uint_as_float(e3.y);
        uint2 u0 = h2[(size_t)e0.x * 32 + lane];
        uint2 u1 = h2[(size_t)e1.x * 32 + lane];
        uint2 u2 = h2[(size_t)e2.x * 32 + lane];
        uint2 u3 = h2[(size_t)e3.x * 32 + lane];
        float2 a0 = __bfloat1622float2(*(const __nv_bfloat162*)&u0.x);
        float2 b0 = __bfloat1622float2(*(const __nv_bfloat162*)&u0.y);
        float2 a1 = __bfloat1622float2(*(const __nv_bfloat162*)&u1.x);
        float2 b1 = __bfloat1622float2(*(const __nv_bfloat162*)&u1.y);
        float2 a2 = __bfloat1622float2(*(const __nv_bfloat162*)&u2.x);
        float2 b2 = __bfloat1622float2(*(const __nv_bfloat162*)&u2.y);
        float2 a3 = __bfloat1622float2(*(const __nv_bfloat162*)&u3.x);
        float2 b3 = __bfloat1622float2(*(const __nv_bfloat162*)&u3.y);
        acc.x = fmaf(w0, a0.x, acc.x); acc.y = fmaf(w0, a0.y, acc.y);
        acc.z = fmaf(w0, b0.x, acc.z); acc.w = fmaf(w0, b0.y, acc.w);
        acc.x = fmaf(w1, a1.x, acc.x); acc.y = fmaf(w1, a1.y, acc.y);
        acc.z = fmaf(w1, b1.x, acc.z); acc.w = fmaf(w1, b1.y, acc.w);
        acc.x = fmaf(w2, a2.x, acc.x); acc.y = fmaf(w2, a2.y, acc.y);
        acc.z = fmaf(w2, b2.x, acc.z); acc.w = fmaf(w2, b2.y, acc.w);
        acc.x = fmaf(w3, a3.x, acc.x); acc.y = fmaf(w3, a3.y, acc.y);
        acc.z = fmaf(w3, b3.x, acc.z); acc.w = fmaf(w3, b3.y, acc.w);
    }
    for (; j < end; j++) {
        uint2 ed = g_edge[j];
        float w = __uint_as_float(ed.y);
        uint2 u = h2[(size_t)ed.x * 32 + lane];
        float2 f0 = __bfloat1622float2(*(const __nv_bfloat162*)&u.x);
        float2 f1 = __bfloat1622float2(*(const __nv_bfloat162*)&u.y);
        acc.x = fmaf(w, f0.x, acc.x); acc.y = fmaf(w, f0.y, acc.y);
        acc.z = fmaf(w, f1.x, acc.z); acc.w = fmaf(w, f1.y, acc.w);
    }
    return acc;
}

// ---------------- layer-1 aggregation: out packed bf16 (GEMM2 A) ----------------
__global__ __launch_bounds__(256)
void agg_h128(const unsigned* __restrict__ hb, unsigned* __restrict__ outb,
              const float* __restrict__ bias, int n) {
    int gw = (blockIdx.x * blockDim.x + threadIdx.x) >> 5;
    if (gw >= n) return;
    int lane = threadIdx.x & 31;
    float di = g_dinv[gw];
    float4 acc = gather_node((const uint2*)hb, gw, lane, di);

    float4 bb = ((const float4*)bias)[lane];
    acc.x = fmaxf(fmaf(acc.x, di, bb.x), 0.f);
    acc.y = fmaxf(fmaf(acc.y, di, bb.y), 0.f);
    acc.z = fmaxf(fmaf(acc.z, di, bb.z), 0.f);
    acc.w = fmaxf(fmaf(acc.w, di, bb.w), 0.f);

    __nv_bfloat162 v0 = __float22bfloat162_rn(make_float2(acc.x, acc.y));
    __nv_bfloat162 v1 = __float22bfloat162_rn(make_float2(acc.z, acc.w));
    ((uint2*)outb)[(size_t)gw * 32 + lane] = make_uint2(*(unsigned*)&v0, *(unsigned*)&v1);
}

// ---------------- layer-2 aggregation + fused W3 projection ----------------
__global__ __launch_bounds__(512)
void agg_h128_w3(const unsigned* __restrict__ hb, const float* __restrict__ bias,
                 const float* __restrict__ W3, int n) {
    __shared__ float Wsc[CCNT][HDIM];
    for (int idx = threadIdx.x; idx < HDIM * CCNT; idx += 512) {
        int k = idx / CCNT, c = idx % CCNT;
        Wsc[c][k] = W3[idx];
    }
    __syncthreads();

    int gw = (blockIdx.x * blockDim.x + threadIdx.x) >> 5;
    if (gw >= n) return;
    int lane = threadIdx.x & 31;
    float di = g_dinv[gw];
    float4 acc = gather_node((const uint2*)hb, gw, lane, di);

    float4 bb = ((const float4*)bias)[lane];
    acc.x = fmaxf(fmaf(acc.x, di, bb.x), 0.f);
    acc.y = fmaxf(fmaf(acc.y, di, bb.y), 0.f);
    acc.z = fmaxf(fmaf(acc.z, di, bb.z), 0.f);
    acc.w = fmaxf(fmaf(acc.w, di, bb.w), 0.f);

    float p[CCNT];
#pragma unroll
    for (int c = 0; c < CCNT; c++) {
        float4 w = *(const float4*)&Wsc[c][4 * lane];
        p[c] = acc.x * w.x + acc.y * w.y + acc.z * w.z + acc.w * w.w;
    }
#pragma unroll
    for (int c = 0; c < CCNT; c++) {
#pragma unroll
        for (int off = 16; off > 0; off >>= 1)
            p[c] += __shfl_xor_sync(0xffffffffu, p[c], off);
    }
    if (lane == 0) {
        float* dst = &g_h3[(size_t)gw * 16];
#pragma unroll
        for (int c = 0; c < CCNT; c++) dst[c] = p[c];
    }
}

// ---------------- layer 3 aggregation + pool ----------------
__global__ __launch_bounds__(256)
void agg_c16_pool(const int* __restrict__ batch, const float* __restrict__ b3, int n) {
    int gw = (blockIdx.x * blockDim.x + threadIdx.x) >> 5;
    if (gw >= n) return;
    int lane = threadIdx.x & 31;
    bool active = (lane < CCNT);

    float di = g_dinv[gw];
    float acc = 0.0f;
    if (active) acc = g_h3[gw * 16 + lane] * di;

    int j = g_row[gw];
    int end = g_row[gw + 1];
    for (; j + 4 <= end; j += 4) {
        uint2 e0 = g_edge[j], e1 = g_edge[j + 1], e2 = g_edge[j + 2], e3 = g_edge[j + 3];
        if (active) {
            acc = fmaf(__uint_as_float(e0.y), g_h3[(size_t)e0.x * 16 + lane], acc);
            acc = fmaf(__uint_as_float(e1.y), g_h3[(size_t)e1.x * 16 + lane], acc);
            acc = fmaf(__uint_as_float(e2.y), g_h3[(size_t)e2.x * 16 + lane], acc);
            acc = fmaf(__uint_as_float(e3.y), g_h3[(size_t)e3.x * 16 + lane], acc);
        }
    }
    for (; j < end; j++) {
        uint2 ed = g_edge[j];
        if (active) acc = fmaf(__uint_as_float(ed.y), g_h3[(size_t)ed.x * 16 + lane], acc);
    }

    int g = batch[gw];
    if (active) {
        acc = fmaf(acc, di, b3[lane]);
        atomicAdd(&g_psum[g * CCNT + lane], acc);
    }
    if (lane == 0) atomicAdd(&g_pcnt[g], 1.0f);
}

// ---------------- final: mean + log_softmax ----------------
__global__ void k_finalize(float* __restrict__ out) {
    int g = threadIdx.x;
    if (g >= GCNT) return;
    float c = fmaxf(g_pcnt[g], 1.0f);
    float v[CCNT];
    float m = -1e30f;
#pragma unroll
    for (int j = 0; j < CCNT; j++) {
        v[j] = g_psum[g * CCNT + j] / c;
        m = fmaxf(m, v[j]);
    }
    float s = 0.0f;
#pragma unroll
    for (int j = 0; j < CCNT; j++) s += expf(v[j] - m);
    float lse = logf(s) + m;
#pragma unroll
    for (int j = 0; j < CCNT; j++) out[g * CCNT + j] = v[j] - lse;
}

// ---------------- launch ----------------
extern "C" void kernel_launch(void* const* d_in, const int* in_sizes, int n_in,
                              void* d_out, int out_size) {
    const float* x    = (const float*)d_in[0];
    const int*   ei   = (const int*)d_in[1];
    const float* ea   = (const float*)d_in[2];
    const int*   bat  = (const int*)d_in[3];
    const float* W1   = (const float*)d_in[4];
    const float* b1   = (const float*)d_in[5];
    const float* W2   = (const float*)d_in[6];
    const float* b2   = (const float*)d_in[7];
    const float* W3   = (const float*)d_in[8];
    const float* b3   = (const float*)d_in[9];
    float* out = (float*)d_out;

    int n = in_sizes[0] / HDIM;   // 50000
    int e = in_sizes[1] / 2;      // 800000
    const int* src = ei;
    const int* dst = ei + e;

    unsigned *ghb, *gaggb;
    cudaGetSymbolAddress((void**)&ghb, g_hb);
    cudaGetSymbolAddress((void**)&gaggb, g_aggb);

    int nb = (n + SCAN_BLK - 1) / SCAN_BLK;   // 98 <= 148 SMs (barrier safety)
    int gemmBlocks = (n + 127) / 128;
    int aggBlocks256 = (n * 32 + 255) / 256;
    int aggBlocks512 = (n * 32 + 511) / 512;

    cudaStream_t s0 = (cudaStream_t)0;

    // fork a side stream: layer-1 GEMM is independent of CSR preprocessing
    cudaStream_t s2;
    cudaStreamCreateWithFlags(&s2, cudaStreamNonBlocking);
    cudaEvent_t evFork, evJoin;
    cudaEventCreateWithFlags(&evFork, cudaEventDisableTiming);
    cudaEventCreateWithFlags(&evJoin, cudaEventDisableTiming);

    cudaEventRecord(evFork, s0);
    cudaStreamWaitEvent(s2, evFork, 0);
    sgemm128_tf32<false><<<gemmBlocks, 256, 0, s2>>>(x, W1, ghb, n);  // h = x@W1
    cudaEventRecord(evJoin, s2);

    // preprocessing on main stream (concurrent with the GEMM above)
    k_init<<<(n + 255) / 256, 256, 0, s0>>>(n);
    k_count<<<(e + 255) / 256, 256, 0, s0>>>(dst, ea, e);
    k_scan<<<nb, SCAN_BLK, 0, s0>>>(n, e, nb);
    k_scatter<<<(e + 255) / 256, 256, 0, s0>>>(src, dst, ea, e);

    // join: aggregation needs both CSR and h
    cudaStreamWaitEvent(s0, evJoin, 0);
    agg_h128<<<aggBlocks256, 256, 0, s0>>>(ghb, gaggb, b1, n);

    // layer 2 (bf16 A) + fused W3 projection
    sgemm128_tf32<true><<<gemmBlocks, 256, 0, s0>>>(gaggb, W2, ghb, n);
    agg_h128_w3<<<aggBlocks512, 512, 0, s0>>>(ghb, b2, W3, n);

    // layer 3 aggregation + pool, then finalize
    agg_c16_pool<<<aggBlocks256, 256, 0, s0>>>(bat, b3, n);
    k_finalize<<<1, 128, 0, s0>>>(out);
    // NOTE: s2/events intentionally not destroyed — kernel_launch is invoked
    // only for the correctness run and one graph capture.
}

// round 16
// speedup vs baseline: 1.3816x; 1.0202x over previous
#include <cuda_runtime.h>
#include <cuda_bf16.h>
#include <math.h>

// Problem constants
#define NMAX 50000
#define EMAX 800000
#define HDIM 128
#define GCNT 128
#define CCNT 10
#define SCAN_BLK 512

// ---------------- device scratch (no cudaMalloc allowed) ----------------
__device__ unsigned g_hb[NMAX * 64];    // GEMM output, packed bf16x2
__device__ unsigned g_aggb[NMAX * 64];  // agg1 output, packed bf16x2 (GEMM2 A)
__device__ float g_h3[NMAX * 16];       // layer-3 projected features (padded C)
__device__ float g_deg[NMAX];
__device__ float g_dinv[NMAX];
__device__ int   g_cnt[NMAX];
__device__ int   g_row[NMAX + 1];
__device__ int   g_cur[NMAX];
__device__ int   g_bsum[128];
__device__ uint2 g_edge[EMAX];          // packed (src, bits(ew*dinv[src]))
__device__ float g_psum[GCNT * CCNT];
__device__ float g_pcnt[GCNT];

// ---------------- preprocessing ----------------

__global__ void k_init(int n) {
    int i = blockIdx.x * blockDim.x + threadIdx.x;
    if (i < n) { g_deg[i] = 1.0f; g_cnt[i] = 0; }   // self-loop weight 1
    if (i < GCNT * CCNT) g_psum[i] = 0.0f;
    if (i < GCNT) g_pcnt[i] = 0.0f;
}

__global__ void k_count(const int* __restrict__ dst, const float* __restrict__ ew, int e) {
    int i = blockIdx.x * blockDim.x + threadIdx.x;
    if (i >= e) return;
    int d = dst[i];
    atomicAdd(&g_deg[d], ew[i]);
    atomicAdd(&g_cnt[d], 1);
}

__global__ void k_scan1(int n) {
    __shared__ int sd[SCAN_BLK];
    int tid = threadIdx.x;
    int i = blockIdx.x * SCAN_BLK + tid;
    int v = (i < n) ? g_cnt[i] : 0;
    sd[tid] = v;
    __syncthreads();
#pragma unroll
    for (int off = 1; off < SCAN_BLK; off <<= 1) {
        int t = (tid >= off) ? sd[tid - off] : 0;
        __syncthreads();
        sd[tid] += t;
        __syncthreads();
    }
    if (i < n) g_row[i] = sd[tid] - v;
    if (tid == SCAN_BLK - 1) g_bsum[blockIdx.x] = sd[SCAN_BLK - 1];
}

// scan3 with scan2 folded in: each block sums the preceding block-sums itself.
__global__ void k_scan3(int n, int e, int nb) {
    __shared__ int sb[128];
    int tid = threadIdx.x;
    if (tid < 128) sb[tid] = (tid < nb) ? g_bsum[tid] : 0;
    __syncthreads();
    int b = blockIdx.x;
    int off = 0;
    for (int k = 0; k < b; k++) off += sb[k];
    int i = b * SCAN_BLK + tid;
    if (i < n) {
        int r = g_row[i] + off;
        g_row[i] = r;
        g_cur[i] = r;
        float d = g_deg[i];
        g_dinv[i] = (d > 0.0f) ? rsqrtf(d) : 0.0f;
    }
    if (b == 0 && tid == 0) g_row[n] = e;
}

__global__ void k_scatter(const int* __restrict__ src, const int* __restrict__ dst,
                          const float* __restrict__ ew, int e) {
    int i = blockIdx.x * blockDim.x + threadIdx.x;
    if (i >= e) return;
    int s = src[i], d = dst[i];
    int pos = atomicAdd(&g_cur[d], 1);
    g_edge[pos] = make_uint2((unsigned)s, __float_as_uint(ew[i] * g_dinv[s]));
}

// ---------------- tensor-core GEMM (single tf32, cvt-at-load) ----------------
// [M,128] @ [128,128] -> bf16x2. A is fp32 (cvt.rna->tf32) or bf16 (exact).
__device__ __forceinline__ void mma_tf32(float* c, const unsigned* a,
                                         unsigned b0, unsigned b1) {
    asm volatile(
        "mma.sync.aligned.m16n8k8.row.col.f32.tf32.tf32.f32 "
        "{%0,%1,%2,%3}, {%4,%5,%6,%7}, {%8,%9}, {%0,%1,%2,%3};\n"
        : "+f"(c[0]), "+f"(c[1]), "+f"(c[2]), "+f"(c[3])
        : "r"(a[0]), "r"(a[1]), "r"(a[2]), "r"(a[3]), "r"(b0), "r"(b1));
}

__device__ __forceinline__ float to_tf32(float v) {
    float r;
    asm("cvt.rna.tf32.f32 %0, %1;" : "=f"(r) : "f"(v));
    return r;
}

template<bool BF16A>
__device__ __forceinline__ void loadA8(const void* Abase, size_t row, int col,
                                       bool ok, float* v) {
    if (!ok) {
#pragma unroll
        for (int q = 0; q < 8; q++) v[q] = 0.0f;
        return;
    }
    if (BF16A) {
        const __nv_bfloat16* A = (const __nv_bfloat16*)Abase;
        uint4 u = *(const uint4*)(A + row * 128 + col);
        float2 f0 = __bfloat1622float2(*(const __nv_bfloat162*)&u.x);
        float2 f1 = __bfloat1622float2(*(const __nv_bfloat162*)&u.y);
        float2 f2 = __bfloat1622float2(*(const __nv_bfloat162*)&u.z);
        float2 f3 = __bfloat1622float2(*(const __nv_bfloat162*)&u.w);
        v[0] = f0.x; v[1] = f0.y; v[2] = f1.x; v[3] = f1.y;
        v[4] = f2.x; v[5] = f2.y; v[6] = f3.x; v[7] = f3.y;   // bf16 ⊂ tf32: exact
    } else {
        const float* A = (const float*)Abase;
        float4 a0 = *(const float4*)(A + row * 128 + col);
        float4 a1 = *(const float4*)(A + row * 128 + col + 4);
        v[0] = to_tf32(a0.x); v[1] = to_tf32(a0.y); v[2] = to_tf32(a0.z); v[3] = to_tf32(a0.w);
        v[4] = to_tf32(a1.x); v[5] = to_tf32(a1.y); v[6] = to_tf32(a1.z); v[7] = to_tf32(a1.w);
    }
}

template<bool BF16A>
__global__ __launch_bounds__(256, 2)
void sgemm128_tf32(const void* __restrict__ A, const float* __restrict__ B,
                   unsigned* __restrict__ Cb, int M) {
    __shared__ float As[2][128][20];
    __shared__ float Bs[2][16][136];

    int tid  = threadIdx.x;
    int warp = tid >> 5;
    int lane = tid & 31;
    int g = lane >> 2;
    int t = lane & 3;
    int r0 = warp * 16;
    int rowBase = blockIdx.x * 128;

    int aRow = tid >> 1;
    int aOff = (tid & 1) * 8;
    int bRow = tid >> 4;
    int bOff = (tid & 15) * 8;

    bool aOk = (rowBase + aRow) < M;
    size_t aGRow = (size_t)(aOk ? rowBase + aRow : 0);

    float acc[16][4];
#pragma unroll
    for (int j = 0; j < 16; j++)
#pragma unroll
        for (int q = 0; q < 4; q++) acc[j][q] = 0.0f;

    // preload stage 0
    {
        float av[8];
        loadA8<BF16A>(A, aGRow, aOff, aOk, av);
#pragma unroll
        for (int q = 0; q < 8; q++) As[0][aRow][aOff + q] = av[q];
        float4 b0 = *(const float4*)(B + (size_t)bRow * 128 + bOff);
        float4 b1 = *(const float4*)(B + (size_t)bRow * 128 + bOff + 4);
        Bs[0][bRow][bOff + 0] = to_tf32(b0.x); Bs[0][bRow][bOff + 1] = to_tf32(b0.y);
        Bs[0][bRow][bOff + 2] = to_tf32(b0.z); Bs[0][bRow][bOff + 3] = to_tf32(b0.w);
        Bs[0][bRow][bOff + 4] = to_tf32(b1.x); Bs[0][bRow][bOff + 5] = to_tf32(b1.y);
        Bs[0][bRow][bOff + 6] = to_tf32(b1.z); Bs[0][bRow][bOff + 7] = to_tf32(b1.w);
    }
    __syncthreads();

    int p = 0;
    for (int k0 = 0; k0 < 128; k0 += 16) {
        bool more = (k0 + 16) < 128;
        float pav[8];
        float4 pb0, pb1;
        if (more) {
            loadA8<BF16A>(A, aGRow, k0 + 16 + aOff, aOk, pav);
            pb0 = *(const float4*)(B + (size_t)(k0 + 16 + bRow) * 128 + bOff);
            pb1 = *(const float4*)(B + (size_t)(k0 + 16 + bRow) * 128 + bOff + 4);
        }

#pragma unroll
        for (int kk = 0; kk < 16; kk += 8) {
            unsigned a[4];
            a[0] = __float_as_uint(As[p][r0 + g    ][kk + t]);
            a[1] = __float_as_uint(As[p][r0 + g + 8][kk + t]);
            a[2] = __float_as_uint(As[p][r0 + g    ][kk + t + 4]);
            a[3] = __float_as_uint(As[p][r0 + g + 8][kk + t + 4]);
#pragma unroll
            for (int j = 0; j < 16; j++) {
                unsigned b0 = __float_as_uint(Bs[p][kk + t    ][j * 8 + g]);
                unsigned b1 = __float_as_uint(Bs[p][kk + t + 4][j * 8 + g]);
                mma_tf32(acc[j], a, b0, b1);
            }
        }

        if (more) {
            int q = p ^ 1;
#pragma unroll
            for (int qq = 0; qq < 8; qq++) As[q][aRow][aOff + qq] = pav[qq];
            Bs[q][bRow][bOff + 0] = to_tf32(pb0.x); Bs[q][bRow][bOff + 1] = to_tf32(pb0.y);
            Bs[q][bRow][bOff + 2] = to_tf32(pb0.z); Bs[q][bRow][bOff + 3] = to_tf32(pb0.w);
            Bs[q][bRow][bOff + 4] = to_tf32(pb1.x); Bs[q][bRow][bOff + 5] = to_tf32(pb1.y);
            Bs[q][bRow][bOff + 6] = to_tf32(pb1.z); Bs[q][bRow][bOff + 7] = to_tf32(pb1.w);
            __syncthreads();
            p = q;
        }
    }

    int rA = rowBase + r0 + g;
    int rB = rA + 8;
#pragma unroll
    for (int j = 0; j < 16; j++) {
        int widx = j * 4 + t;
        if (rA < M) {
            __nv_bfloat162 v = __float22bfloat162_rn(make_float2(acc[j][0], acc[j][1]));
            Cb[(size_t)rA * 64 + widx] = *(unsigned*)&v;
        }
        if (rB < M) {
            __nv_bfloat162 v = __float22bfloat162_rn(make_float2(acc[j][2], acc[j][3]));
            Cb[(size_t)rB * 64 + widx] = *(unsigned*)&v;
        }
    }
}

// ---------------- shared gather body (bf16 in, fp32 acc, 8-edge unroll) ------
__device__ __forceinline__ void fma_bf16x4(float4& acc, float w, uint2 u) {
    float2 f0 = __bfloat1622float2(*(const __nv_bfloat162*)&u.x);
    float2 f1 = __bfloat1622float2(*(const __nv_bfloat162*)&u.y);
    acc.x = fmaf(w, f0.x, acc.x); acc.y = fmaf(w, f0.y, acc.y);
    acc.z = fmaf(w, f1.x, acc.z); acc.w = fmaf(w, f1.y, acc.w);
}

__device__ __forceinline__ float4 gather_node(const uint2* __restrict__ h2,
                                              int gw, int lane, float di) {
    float4 acc;
    {
        uint2 u = h2[(size_t)gw * 32 + lane];
        float2 f0 = __bfloat1622float2(*(const __nv_bfloat162*)&u.x);
        float2 f1 = __bfloat1622float2(*(const __nv_bfloat162*)&u.y);
        acc.x = f0.x * di; acc.y = f0.y * di;
        acc.z = f1.x * di; acc.w = f1.y * di;
    }
    int j = g_row[gw];
    int end = g_row[gw + 1];

    // 8-edge batches: 8 outstanding gathers per warp (double the MLP of 4x)
    for (; j + 8 <= end; j += 8) {
        uint2 e0 = g_edge[j],     e1 = g_edge[j + 1], e2 = g_edge[j + 2], e3 = g_edge[j + 3];
        uint2 e4 = g_edge[j + 4], e5 = g_edge[j + 5], e6 = g_edge[j + 6], e7 = g_edge[j + 7];
        uint2 u0 = h2[(size_t)e0.x * 32 + lane];
        uint2 u1 = h2[(size_t)e1.x * 32 + lane];
        uint2 u2 = h2[(size_t)e2.x * 32 + lane];
        uint2 u3 = h2[(size_t)e3.x * 32 + lane];
        uint2 u4 = h2[(size_t)e4.x * 32 + lane];
        uint2 u5 = h2[(size_t)e5.x * 32 + lane];
        uint2 u6 = h2[(size_t)e6.x * 32 + lane];
        uint2 u7 = h2[(size_t)e7.x * 32 + lane];
        fma_bf16x4(acc, __uint_as_float(e0.y), u0);
        fma_bf16x4(acc, __uint_as_float(e1.y), u1);
        fma_bf16x4(acc, __uint_as_float(e2.y), u2);
        fma_bf16x4(acc, __uint_as_float(e3.y), u3);
        fma_bf16x4(acc, __uint_as_float(e4.y), u4);
        fma_bf16x4(acc, __uint_as_float(e5.y), u5);
        fma_bf16x4(acc, __uint_as_float(e6.y), u6);
        fma_bf16x4(acc, __uint_as_float(e7.y), u7);
    }
    for (; j + 4 <= end; j += 4) {
        uint2 e0 = g_edge[j], e1 = g_edge[j + 1], e2 = g_edge[j + 2], e3 = g_edge[j + 3];
        uint2 u0 = h2[(size_t)e0.x * 32 + lane];
        uint2 u1 = h2[(size_t)e1.x * 32 + lane];
        uint2 u2 = h2[(size_t)e2.x * 32 + lane];
        uint2 u3 = h2[(size_t)e3.x * 32 + lane];
        fma_bf16x4(acc, __uint_as_float(e0.y), u0);
        fma_bf16x4(acc, __uint_as_float(e1.y), u1);
        fma_bf16x4(acc, __uint_as_float(e2.y), u2);
        fma_bf16x4(acc, __uint_as_float(e3.y), u3);
    }
    for (; j < end; j++) {
        uint2 ed = g_edge[j];
        uint2 u = h2[(size_t)ed.x * 32 + lane];
        fma_bf16x4(acc, __uint_as_float(ed.y), u);
    }
    return acc;
}

// ---------------- layer-1 aggregation: out packed bf16 (GEMM2 A) ----------------
__global__ __launch_bounds__(256)
void agg_h128(const unsigned* __restrict__ hb, unsigned* __restrict__ outb,
              const float* __restrict__ bias, int n) {
    int gw = (blockIdx.x * blockDim.x + threadIdx.x) >> 5;
    if (gw >= n) return;
    int lane = threadIdx.x & 31;
    float di = g_dinv[gw];
    float4 acc = gather_node((const uint2*)hb, gw, lane, di);

    float4 bb = ((const float4*)bias)[lane];
    acc.x = fmaxf(fmaf(acc.x, di, bb.x), 0.f);
    acc.y = fmaxf(fmaf(acc.y, di, bb.y), 0.f);
    acc.z = fmaxf(fmaf(acc.z, di, bb.z), 0.f);
    acc.w = fmaxf(fmaf(acc.w, di, bb.w), 0.f);

    __nv_bfloat162 v0 = __float22bfloat162_rn(make_float2(acc.x, acc.y));
    __nv_bfloat162 v1 = __float22bfloat162_rn(make_float2(acc.z, acc.w));
    ((uint2*)outb)[(size_t)gw * 32 + lane] = make_uint2(*(unsigned*)&v0, *(unsigned*)&v1);
}

// ---------------- layer-2 aggregation + fused W3 projection ----------------
__global__ __launch_bounds__(512)
void agg_h128_w3(const unsigned* __restrict__ hb, const float* __restrict__ bias,
                 const float* __restrict__ W3, int n) {
    __shared__ float Wsc[CCNT][HDIM];
    for (int idx = threadIdx.x; idx < HDIM * CCNT; idx += 512) {
        int k = idx / CCNT, c = idx % CCNT;
        Wsc[c][k] = W3[idx];
    }
    __syncthreads();

    int gw = (blockIdx.x * blockDim.x + threadIdx.x) >> 5;
    if (gw >= n) return;
    int lane = threadIdx.x & 31;
    float di = g_dinv[gw];
    float4 acc = gather_node((const uint2*)hb, gw, lane, di);

    float4 bb = ((const float4*)bias)[lane];
    acc.x = fmaxf(fmaf(acc.x, di, bb.x), 0.f);
    acc.y = fmaxf(fmaf(acc.y, di, bb.y), 0.f);
    acc.z = fmaxf(fmaf(acc.z, di, bb.z), 0.f);
    acc.w = fmaxf(fmaf(acc.w, di, bb.w), 0.f);

    float p[CCNT];
#pragma unroll
    for (int c = 0; c < CCNT; c++) {
        float4 w = *(const float4*)&Wsc[c][4 * lane];
        p[c] = acc.x * w.x + acc.y * w.y + acc.z * w.z + acc.w * w.w;
    }
#pragma unroll
    for (int c = 0; c < CCNT; c++) {
#pragma unroll
        for (int off = 16; off > 0; off >>= 1)
            p[c] += __shfl_xor_sync(0xffffffffu, p[c], off);
    }
    if (lane == 0) {
        float* dst = &g_h3[(size_t)gw * 16];
#pragma unroll
        for (int c = 0; c < CCNT; c++) dst[c] = p[c];
    }
}

// ---------------- layer 3 aggregation + pool ----------------
__global__ __launch_bounds__(256)
void agg_c16_pool(const int* __restrict__ batch, const float* __restrict__ b3, int n) {
    int gw = (blockIdx.x * blockDim.x + threadIdx.x) >> 5;
    if (gw >= n) return;
    int lane = threadIdx.x & 31;
    bool active = (lane < CCNT);

    float di = g_dinv[gw];
    float acc = 0.0f;
    if (active) acc = g_h3[gw * 16 + lane] * di;

    int j = g_row[gw];
    int end = g_row[gw + 1];
    for (; j + 4 <= end; j += 4) {
        uint2 e0 = g_edge[j], e1 = g_edge[j + 1], e2 = g_edge[j + 2], e3 = g_edge[j + 3];
        if (active) {
            acc = fmaf(__uint_as_float(e0.y), g_h3[(size_t)e0.x * 16 + lane], acc);
            acc = fmaf(__uint_as_float(e1.y), g_h3[(size_t)e1.x * 16 + lane], acc);
            acc = fmaf(__uint_as_float(e2.y), g_h3[(size_t)e2.x * 16 + lane], acc);
            acc = fmaf(__uint_as_float(e3.y), g_h3[(size_t)e3.x * 16 + lane], acc);
        }
    }
    for (; j < end; j++) {
        uint2 ed = g_edge[j];
        if (active) acc = fmaf(__uint_as_float(ed.y), g_h3[(size_t)ed.x * 16 + lane], acc);
    }

    int g = batch[gw];
    if (active) {
        acc = fmaf(acc, di, b3[lane]);
        atomicAdd(&g_psum[g * CCNT + lane], acc);
    }
    if (lane == 0) atomicAdd(&g_pcnt[g], 1.0f);
}

// ---------------- final: mean + log_softmax ----------------
__global__ void k_finalize(float* __restrict__ out) {
    int g = threadIdx.x;
    if (g >= GCNT) return;
    float c = fmaxf(g_pcnt[g], 1.0f);
    float v[CCNT];
    float m = -1e30f;
#pragma unroll
    for (int j = 0; j < CCNT; j++) {
        v[j] = g_psum[g * CCNT + j] / c;
        m = fmaxf(m, v[j]);
    }
    float s = 0.0f;
#pragma unroll
    for (int j = 0; j < CCNT; j++) s += expf(v[j] - m);
    float lse = logf(s) + m;
#pragma unroll
    for (int j = 0; j < CCNT; j++) out[g * CCNT + j] = v[j] - lse;
}

// ---------------- launch ----------------
extern "C" void kernel_launch(void* const* d_in, const int* in_sizes, int n_in,
                              void* d_out, int out_size) {
    const float* x    = (const float*)d_in[0];
    const int*   ei   = (const int*)d_in[1];
    const float* ea   = (const float*)d_in[2];
    const int*   bat  = (const int*)d_in[3];
    const float* W1   = (const float*)d_in[4];
    const float* b1   = (const float*)d_in[5];
    const float* W2   = (const float*)d_in[6];
    const float* b2   = (const float*)d_in[7];
    const float* W3   = (const float*)d_in[8];
    const float* b3   = (const float*)d_in[9];
    float* out = (float*)d_out;

    int n = in_sizes[0] / HDIM;   // 50000
    int e = in_sizes[1] / 2;      // 800000
    const int* src = ei;
    const int* dst = ei + e;

    unsigned *ghb, *gaggb;
    cudaGetSymbolAddress((void**)&ghb, g_hb);
    cudaGetSymbolAddress((void**)&gaggb, g_aggb);

    int nb = (n + SCAN_BLK - 1) / SCAN_BLK;
    int gemmBlocks = (n + 127) / 128;
    int aggBlocks256 = (n * 32 + 255) / 256;
    int aggBlocks512 = (n * 32 + 511) / 512;

    cudaStream_t s0 = (cudaStream_t)0;

    // fork a side stream: layer-1 GEMM is independent of CSR preprocessing
    cudaStream_t s2;
    cudaStreamCreateWithFlags(&s2, cudaStreamNonBlocking);
    cudaEvent_t evFork, evJoin;
    cudaEventCreateWithFlags(&evFork, cudaEventDisableTiming);
    cudaEventCreateWithFlags(&evJoin, cudaEventDisableTiming);

    cudaEventRecord(evFork, s0);
    cudaStreamWaitEvent(s2, evFork, 0);
    sgemm128_tf32<false><<<gemmBlocks, 256, 0, s2>>>(x, W1, ghb, n);  // h = x@W1
    cudaEventRecord(evJoin, s2);

    // preprocessing on main stream (concurrent with the GEMM above)
    k_init<<<(n + 255) / 256, 256, 0, s0>>>(n);
    k_count<<<(e + 255) / 256, 256, 0, s0>>>(dst, ea, e);
    k_scan1<<<nb, SCAN_BLK, 0, s0>>>(n);
    k_scan3<<<nb, SCAN_BLK, 0, s0>>>(n, e, nb);
    k_scatter<<<(e + 255) / 256, 256, 0, s0>>>(src, dst, ea, e);

    // join: aggregation needs both CSR and h
    cudaStreamWaitEvent(s0, evJoin, 0);
    agg_h128<<<aggBlocks256, 256, 0, s0>>>(ghb, gaggb, b1, n);

    // layer 2 (bf16 A) + fused W3 projection
    sgemm128_tf32<true><<<gemmBlocks, 256, 0, s0>>>(gaggb, W2, ghb, n);
    agg_h128_w3<<<aggBlocks512, 512, 0, s0>>>(ghb, b2, W3, n);

    // layer 3 aggregation + pool, then finalize
    agg_c16_pool<<<aggBlocks256, 256, 0, s0>>>(bat, b3, n);
    k_finalize<<<1, 128, 0, s0>>>(out);
    // NOTE: s2/events intentionally not destroyed — kernel_launch is invoked
    // only for the correctness run and one graph capture.
}